// round 1
// baseline (speedup 1.0000x reference)
#include <cuda_runtime.h>
#include <math.h>

#define NB 4
#define LQ 1000
#define DIM 256
#define HEADS 8
#define DHEAD 32
#define DEPTH 2
#define LVLS 5
#define NPTS 4
#define MLPD 512
#define LIN 21824
#define NQ (NB*LQ)     /* 4000  */
#define NV (NB*LIN)    /* 87296 */

// ---------------- scratch (device globals; no allocations allowed) ----------
__device__ float g_pe [NQ*DIM];
__device__ float g_x  [NQ*DIM];
__device__ float g_xn [NQ*DIM];
__device__ float g_qkv[NQ*3*DIM];
__device__ float g_att[NQ*DIM];
__device__ float g_srcn [NV*DIM];
__device__ float g_value[NV*DIM];
__device__ float g_off[NQ*HEADS*LVLS*NPTS*2];
__device__ float g_awl[NQ*HEADS*LVLS*NPTS];
__device__ float g_aw [NQ*HEADS*LVLS*NPTS];
__device__ float g_ms [NQ*DIM];
__device__ float g_ffh[NQ*MLPD];

__constant__ int c_sz[LVLS]    = {128,64,32,16,8};                 // H==W per level
__constant__ int c_start[LVLS] = {0,16384,20480,21504,21760};

// ---------------- simple copy ----------------------------------------------
__global__ void copy_kernel(const float* __restrict__ in, float* __restrict__ out, int n)
{
    int i = blockIdx.x*256 + threadIdx.x;
    if (i < n) out[i] = in[i];
}

// ---------------- positional embedding: pe = cp @ pos_w + pos_b -------------
__global__ void pe_kernel(const float* __restrict__ cp, const float* __restrict__ pw,
                          const float* __restrict__ pb, float* __restrict__ pe)
{
    int row = blockIdx.x, t = threadIdx.x;
    float a = cp[row*2+0], b = cp[row*2+1];
    pe[(size_t)row*DIM + t] = a*pw[t] + b*pw[DIM+t] + pb[t];
}

// ---------------- LayerNorm (row = 256) with optional pre/post pe add -------
__global__ void __launch_bounds__(256) ln_kernel(
    const float* __restrict__ in, const float* __restrict__ pe,
    const float* __restrict__ g, const float* __restrict__ b,
    float* __restrict__ out, int preAdd, int postAdd)
{
    int row = blockIdx.x, t = threadIdx.x;
    size_t idx = (size_t)row*DIM + t;
    float p = pe ? pe[idx] : 0.f;
    float v = in[idx] + (preAdd ? p : 0.f);

    float s = v, s2 = v*v;
    #pragma unroll
    for (int o = 16; o > 0; o >>= 1) {
        s  += __shfl_xor_sync(0xffffffffu, s,  o);
        s2 += __shfl_xor_sync(0xffffffffu, s2, o);
    }
    __shared__ float sh[8], sh2[8];
    int w = t >> 5, lane = t & 31;
    if (lane == 0) { sh[w] = s; sh2[w] = s2; }
    __syncthreads();
    __shared__ float s_mean, s_rstd;
    if (t == 0) {
        float ts = 0.f, ts2 = 0.f;
        #pragma unroll
        for (int i = 0; i < 8; i++) { ts += sh[i]; ts2 += sh2[i]; }
        float mean = ts * (1.f/DIM);
        float var  = ts2 * (1.f/DIM) - mean*mean;
        s_mean = mean;
        s_rstd = rsqrtf(var + 1e-5f);
    }
    __syncthreads();
    float y = (v - s_mean) * s_rstd * g[t] + b[t];
    if (postAdd) y += p;
    out[idx] = y;
}

// ---------------- generic SGEMM: C = [res +] act(A@W + bias) ----------------
#define BM 64
#define BN 64
#define BK 16
__global__ void __launch_bounds__(256) gemm_kernel(
    const float* __restrict__ A, const float* __restrict__ W,
    const float* __restrict__ bias, const float* __restrict__ res,
    float* __restrict__ C, int M, int K, int N, int gelu)
{
    __shared__ float As[BK][BM+4];
    __shared__ float Bs[BK][BN+4];
    int bm = blockIdx.y*BM, bn = blockIdx.x*BN;
    int tid = threadIdx.x;
    int trow = tid >> 4, tcol = tid & 15;

    float acc[4][4];
    #pragma unroll
    for (int i = 0; i < 4; i++)
        #pragma unroll
        for (int j = 0; j < 4; j++) acc[i][j] = 0.f;

    int mA = tid >> 2, kA = (tid & 3) * 4;     // A: 64 rows x 16 k, float4 per thread
    int kB = tid >> 4, nB = (tid & 15) * 4;    // W: 16 k x 64 n, float4 per thread

    for (int k0 = 0; k0 < K; k0 += BK) {
        {
            int gm = bm + mA;
            float4 a = make_float4(0.f,0.f,0.f,0.f);
            if (gm < M) a = *reinterpret_cast<const float4*>(&A[(size_t)gm*K + k0 + kA]);
            As[kA+0][mA] = a.x; As[kA+1][mA] = a.y; As[kA+2][mA] = a.z; As[kA+3][mA] = a.w;
        }
        {
            int gn = bn + nB;
            float4 b = make_float4(0.f,0.f,0.f,0.f);
            if (gn < N) b = *reinterpret_cast<const float4*>(&W[(size_t)(k0 + kB)*N + gn]);
            *reinterpret_cast<float4*>(&Bs[kB][nB]) = b;
        }
        __syncthreads();
        #pragma unroll
        for (int kk = 0; kk < BK; kk++) {
            float4 ra = *reinterpret_cast<const float4*>(&As[kk][trow*4]);
            float4 rb = *reinterpret_cast<const float4*>(&Bs[kk][tcol*4]);
            float a[4] = {ra.x, ra.y, ra.z, ra.w};
            float b[4] = {rb.x, rb.y, rb.z, rb.w};
            #pragma unroll
            for (int i = 0; i < 4; i++)
                #pragma unroll
                for (int j = 0; j < 4; j++) acc[i][j] += a[i]*b[j];
        }
        __syncthreads();
    }

    const float kC = 0.7978845608028654f;
    #pragma unroll
    for (int i = 0; i < 4; i++) {
        int gm = bm + trow*4 + i;
        if (gm >= M) continue;
        #pragma unroll
        for (int j = 0; j < 4; j++) {
            int gn = bn + tcol*4 + j;
            if (gn >= N) continue;
            float v = acc[i][j];
            if (bias) v += bias[gn];
            if (gelu) v = 0.5f*v*(1.f + tanhf(kC*(v + 0.044715f*v*v*v)));
            if (res)  v += res[(size_t)gm*N + gn];
            C[(size_t)gm*N + gn] = v;
        }
    }
}

// ---------------- self-attention (flash-style, d=32) ------------------------
__global__ void __launch_bounds__(128) attn_kernel(const float* __restrict__ qkv,
                                                   float* __restrict__ out)
{
    int n = blockIdx.z, h = blockIdx.y;
    int qi = blockIdx.x*128 + threadIdx.x;
    bool act = qi < LQ;

    float q[DHEAD];
    {
        const float* qr = qkv + (size_t)(n*LQ + (act ? qi : 0))*(3*DIM) + h*DHEAD;
        #pragma unroll
        for (int d = 0; d < DHEAD; d++) q[d] = qr[d];
    }
    float o[DHEAD];
    #pragma unroll
    for (int d = 0; d < DHEAD; d++) o[d] = 0.f;
    float mmax = -1e30f, lsum = 0.f;

    __shared__ float ks[32][DHEAD+1], vs[32][DHEAD+1];

    for (int k0 = 0; k0 < LQ; k0 += 32) {
        int nk = min(32, LQ - k0);
        __syncthreads();
        for (int t = threadIdx.x; t < nk*DHEAD; t += 128) {
            int j = t >> 5, d = t & 31;
            const float* kr = qkv + (size_t)(n*LQ + k0 + j)*(3*DIM);
            ks[j][d] = kr[DIM     + h*DHEAD + d];
            vs[j][d] = kr[2*DIM   + h*DHEAD + d];
        }
        __syncthreads();
        if (act) {
            for (int j = 0; j < nk; j++) {
                float s = 0.f;
                #pragma unroll
                for (int d = 0; d < DHEAD; d++) s += q[d]*ks[j][d];
                s *= 0.17677669529663687f;   // 32^-0.5
                if (s <= mmax) {
                    float e = __expf(s - mmax);
                    lsum += e;
                    #pragma unroll
                    for (int d = 0; d < DHEAD; d++) o[d] += e*vs[j][d];
                } else {
                    float corr = __expf(mmax - s);
                    lsum = lsum*corr + 1.f;
                    #pragma unroll
                    for (int d = 0; d < DHEAD; d++) o[d] = o[d]*corr + vs[j][d];
                    mmax = s;
                }
            }
        }
    }
    if (act) {
        float inv = 1.f/lsum;
        float* orow = out + (size_t)(n*LQ + qi)*DIM + h*DHEAD;
        #pragma unroll
        for (int d = 0; d < DHEAD; d++) orow[d] = o[d]*inv;
    }
}

// ---------------- attention-weight softmax over L*P=20 ----------------------
__global__ void softmax_aw_kernel(const float* __restrict__ in, float* __restrict__ out)
{
    int gid = blockIdx.x*256 + threadIdx.x;
    if (gid >= NQ*HEADS) return;
    size_t base = (size_t)gid * (LVLS*NPTS);
    float m = -1e30f;
    float v[LVLS*NPTS];
    #pragma unroll
    for (int j = 0; j < LVLS*NPTS; j++) { v[j] = in[base+j]; m = fmaxf(m, v[j]); }
    float s = 0.f;
    #pragma unroll
    for (int j = 0; j < LVLS*NPTS; j++) { v[j] = __expf(v[j]-m); s += v[j]; }
    float inv = 1.f/s;
    #pragma unroll
    for (int j = 0; j < LVLS*NPTS; j++) out[base+j] = v[j]*inv;
}

// ---------------- multi-scale deformable sampling ---------------------------
__global__ void __launch_bounds__(256) msdeform_kernel(
    const float* __restrict__ value, const float* __restrict__ cp,
    const float* __restrict__ off, const float* __restrict__ aw,
    float* __restrict__ out)
{
    int nq = blockIdx.x;
    int n  = nq / LQ;
    int t  = threadIdx.x;
    int h  = t >> 5, d = t & 31;
    float cx = cp[nq*2+0], cy = cp[nq*2+1];
    float acc = 0.f;

    #pragma unroll
    for (int l = 0; l < LVLS; l++) {
        int S = c_sz[l];            // H == W
        int st = c_start[l];
        #pragma unroll
        for (int p = 0; p < NPTS; p++) {
            size_t pb = (((size_t)nq*HEADS + h)*LVLS + l)*NPTS + p;
            float w  = aw[pb];
            float gx = cx*S + off[pb*2+0] - 0.5f;
            float gy = cy*S + off[pb*2+1] - 0.5f;
            float x0f = floorf(gx), y0f = floorf(gy);
            float lx = gx - x0f, ly = gy - y0f;
            int x0 = (int)x0f, y0 = (int)y0f;
            int x1 = x0+1, y1 = y0+1;
            const float* vb = value + ((size_t)n*LIN + st)*DIM + h*DHEAD + d;
            float v00 = 0.f, v01 = 0.f, v10 = 0.f, v11 = 0.f;
            bool xi0 = (x0 >= 0) & (x0 < S), xi1 = (x1 >= 0) & (x1 < S);
            bool yi0 = (y0 >= 0) & (y0 < S), yi1 = (y1 >= 0) & (y1 < S);
            if (yi0 & xi0) v00 = vb[(size_t)(y0*S + x0)*DIM];
            if (yi0 & xi1) v01 = vb[(size_t)(y0*S + x1)*DIM];
            if (yi1 & xi0) v10 = vb[(size_t)(y1*S + x0)*DIM];
            if (yi1 & xi1) v11 = vb[(size_t)(y1*S + x1)*DIM];
            float samp = v00*(1.f-ly)*(1.f-lx) + v01*(1.f-ly)*lx
                       + v10*ly*(1.f-lx)       + v11*ly*lx;
            acc += w * samp;
        }
    }
    out[(size_t)nq*DIM + t] = acc;
}

// ---------------- host orchestration ----------------------------------------
static inline void* symaddr(const void* s)
{
    void* p = nullptr;
    cudaGetSymbolAddress(&p, s);
    return p;
}

extern "C" void kernel_launch(void* const* d_in, const int* in_sizes, int n_in,
                              void* d_out, int out_size)
{
    const float* x    = (const float*)d_in[0];
    const float* src  = (const float*)d_in[1];
    const float* cp   = (const float*)d_in[2];
    const float* posw = (const float*)d_in[5];
    const float* posb = (const float*)d_in[6];
    const float* ln1g = (const float*)d_in[7];
    const float* ln1b = (const float*)d_in[8];
    const float* qkvw = (const float*)d_in[9];
    const float* outw = (const float*)d_in[10];
    const float* outb = (const float*)d_in[11];
    const float* ln2g = (const float*)d_in[12];
    const float* ln2b = (const float*)d_in[13];
    const float* offw = (const float*)d_in[14];
    const float* offb = (const float*)d_in[15];
    const float* aww  = (const float*)d_in[16];
    const float* awb  = (const float*)d_in[17];
    const float* valw = (const float*)d_in[18];
    const float* valb = (const float*)d_in[19];
    const float* opw  = (const float*)d_in[20];
    const float* opb  = (const float*)d_in[21];
    const float* ln3g = (const float*)d_in[22];
    const float* ln3b = (const float*)d_in[23];
    const float* ff1w = (const float*)d_in[24];
    const float* ff1b = (const float*)d_in[25];
    const float* ff2w = (const float*)d_in[26];
    const float* ff2b = (const float*)d_in[27];

    float* pe   = (float*)symaddr(g_pe);
    float* xb   = (float*)symaddr(g_x);
    float* xn   = (float*)symaddr(g_xn);
    float* qkv  = (float*)symaddr(g_qkv);
    float* att  = (float*)symaddr(g_att);
    float* srcn = (float*)symaddr(g_srcn);
    float* val  = (float*)symaddr(g_value);
    float* offv = (float*)symaddr(g_off);
    float* awl  = (float*)symaddr(g_awl);
    float* aw   = (float*)symaddr(g_aw);
    float* ms   = (float*)symaddr(g_ms);
    float* ffh  = (float*)symaddr(g_ffh);

    // init
    copy_kernel<<<(NQ*DIM+255)/256, 256>>>(x, xb, NQ*DIM);
    pe_kernel<<<NQ, DIM>>>(cp, posw, posb, pe);

    auto gemm = [](const float* A, const float* W, const float* b, const float* r,
                   float* C, int M, int K, int N, int gelu) {
        dim3 grid((N+BN-1)/BN, (M+BM-1)/BM);
        gemm_kernel<<<grid, 256>>>(A, W, b, r, C, M, K, N, gelu);
    };

    for (int i = 0; i < DEPTH; i++) {
        // ---- self-attention ----
        ln_kernel<<<NQ, DIM>>>(xb, pe, ln1g + i*DIM, ln1b + i*DIM, xn, 1, 0);
        gemm(xn, qkvw + (size_t)i*DIM*3*DIM, nullptr, nullptr, qkv, NQ, DIM, 3*DIM, 0);
        attn_kernel<<<dim3((LQ+127)/128, HEADS, NB), 128>>>(qkv, att);
        gemm(att, outw + (size_t)i*DIM*DIM, outb + i*DIM, xb, xb, NQ, DIM, DIM, 0);

        // ---- deformable cross-attention ----
        ln_kernel<<<NQ, DIM>>>(xb, pe, ln2g + i*DIM, ln2b + i*DIM, xn, 0, 1);   // query = LN(x)+pe
        ln_kernel<<<NV, DIM>>>(src, nullptr, ln2g + i*DIM, ln2b + i*DIM, srcn, 0, 0);
        gemm(srcn, valw + (size_t)i*DIM*DIM, valb + i*DIM, nullptr, val, NV, DIM, DIM, 0);
        gemm(xn, offw + (size_t)i*DIM*(HEADS*LVLS*NPTS*2), offb + i*(HEADS*LVLS*NPTS*2),
             nullptr, offv, NQ, DIM, HEADS*LVLS*NPTS*2, 0);
        gemm(xn, aww + (size_t)i*DIM*(HEADS*LVLS*NPTS), awb + i*(HEADS*LVLS*NPTS),
             nullptr, awl, NQ, DIM, HEADS*LVLS*NPTS, 0);
        softmax_aw_kernel<<<(NQ*HEADS+255)/256, 256>>>(awl, aw);
        msdeform_kernel<<<NQ, 256>>>(val, cp, offv, aw, ms);
        gemm(ms, opw + (size_t)i*DIM*DIM, opb + i*DIM, xb, xb, NQ, DIM, DIM, 0);

        // ---- feedforward ----
        ln_kernel<<<NQ, DIM>>>(xb, nullptr, ln3g + i*DIM, ln3b + i*DIM, xn, 0, 0);
        gemm(xn, ff1w + (size_t)i*DIM*MLPD, ff1b + i*MLPD, nullptr, ffh, NQ, DIM, MLPD, 1);
        gemm(ffh, ff2w + (size_t)i*MLPD*DIM, ff2b + i*DIM, xb, xb, NQ, MLPD, DIM, 0);
    }

    copy_kernel<<<(NQ*DIM+255)/256, 256>>>(xb, (float*)d_out, NQ*DIM);
}